// round 11
// baseline (speedup 1.0000x reference)
#include <cuda_runtime.h>
#include <math.h>

// Problem constants (fixed by the reference: B=2, N=2048, D=1024, H=16, hd=64)
#define BB   2
#define NN   2048
#define DD   1024
#define HH   16
#define HD   64
#define MM   (BB * NN)        // 4096 total tokens
#define ROWS (BB * HH * NN)   // 65536 (b,h,n) rows of length 64

// Scratch: device globals (no allocations allowed)
__device__ float g_q[ROWS * HD];     // (B,H,N,hd)
__device__ float g_k[ROWS * HD];
__device__ float g_v[ROWS * HD];
__device__ float g_q2[ROWS];         // |q|^2 per row
__device__ float g_k2[ROWS];
__device__ float g_att[MM * DD];     // attention output, (B*N, D) with D = H*hd

// ---------------------------------------------------------------------------
// SGEMM: C[m][c] = sum_k A[m][k] * W[c][k] + bias[c]
// A: (M,1024) row-major, W: (1024,1024) row-major (so this is A @ W^T).
// Tile: BM=128, BN=64, BK=16; 256 threads; 8x4 micro-tile per thread.
// MODE 0: C is (M,1024) row-major.
// MODE 1: C is head layout (B,H,N,hd): since BN==hd==64, each block's 64
//         output columns are exactly one head h = blockIdx.x.
// ---------------------------------------------------------------------------
template <int MODE>
__global__ __launch_bounds__(256, 2)
void sgemm_kernel(const float* __restrict__ A, const float* __restrict__ W,
                  const float* __restrict__ bias, float* __restrict__ C)
{
    __shared__ float As[16][128];   // [k][m] transposed for LDS.128 fragments
    __shared__ float Bs[16][64];    // [k][n]

    const int tid = threadIdx.x;
    const int tx  = tid & 15;        // 0..15 -> n micro-cols
    const int ty  = tid >> 4;        // 0..15 -> m micro-rows
    const int m0  = blockIdx.y * 128;
    const int n0  = blockIdx.x * 64;

    const int lrow = tid >> 2;        // 0..63
    const int lk   = (tid & 3) << 2;  // 0,4,8,12

    const float* Ap0 = A + (size_t)(m0 + lrow) * DD + lk;
    const float* Ap1 = Ap0 + (size_t)64 * DD;
    const float* Wp  = W + (size_t)(n0 + lrow) * DD + lk;

    float acc[8][4];
    #pragma unroll
    for (int i = 0; i < 8; i++)
        #pragma unroll
        for (int j = 0; j < 4; j++) acc[i][j] = 0.0f;

    for (int k0 = 0; k0 < DD; k0 += 16) {
        float4 a0 = *(const float4*)(Ap0 + k0);
        float4 a1 = *(const float4*)(Ap1 + k0);
        float4 b0 = *(const float4*)(Wp  + k0);
        As[lk + 0][lrow]      = a0.x;
        As[lk + 1][lrow]      = a0.y;
        As[lk + 2][lrow]      = a0.z;
        As[lk + 3][lrow]      = a0.w;
        As[lk + 0][lrow + 64] = a1.x;
        As[lk + 1][lrow + 64] = a1.y;
        As[lk + 2][lrow + 64] = a1.z;
        As[lk + 3][lrow + 64] = a1.w;
        Bs[lk + 0][lrow]      = b0.x;
        Bs[lk + 1][lrow]      = b0.y;
        Bs[lk + 2][lrow]      = b0.z;
        Bs[lk + 3][lrow]      = b0.w;
        __syncthreads();

        #pragma unroll
        for (int kk = 0; kk < 16; kk++) {
            float4 af0 = *(const float4*)&As[kk][ty * 8];
            float4 af1 = *(const float4*)&As[kk][ty * 8 + 4];
            float4 bf  = *(const float4*)&Bs[kk][tx * 4];
            float am[8] = {af0.x, af0.y, af0.z, af0.w, af1.x, af1.y, af1.z, af1.w};
            float bm[4] = {bf.x, bf.y, bf.z, bf.w};
            #pragma unroll
            for (int i = 0; i < 8; i++)
                #pragma unroll
                for (int j = 0; j < 4; j++)
                    acc[i][j] = fmaf(am[i], bm[j], acc[i][j]);
        }
        __syncthreads();
    }

    const float4 bv = *(const float4*)(bias + n0 + tx * 4);
    #pragma unroll
    for (int i = 0; i < 8; i++) {
        const int m = m0 + ty * 8 + i;
        float4 o;
        o.x = acc[i][0] + bv.x;
        o.y = acc[i][1] + bv.y;
        o.z = acc[i][2] + bv.z;
        o.w = acc[i][3] + bv.w;
        if (MODE == 0) {
            *(float4*)(C + (size_t)m * DD + n0 + tx * 4) = o;
        } else {
            const int b = m >> 11;        // m / 2048
            const int n = m & 2047;
            const int h = n0 >> 6;        // one head per 64-col tile
            *(float4*)(C + (((size_t)(b * HH + h)) * NN + n) * HD + tx * 4) = o;
        }
    }
}

// ---------------------------------------------------------------------------
// Row squared-norm over the last dim (64) of (B,H,N,hd)
// ---------------------------------------------------------------------------
__global__ __launch_bounds__(256)
void rownorm_kernel(const float* __restrict__ a, float* __restrict__ o)
{
    const int r = blockIdx.x * blockDim.x + threadIdx.x;
    if (r >= ROWS) return;
    const float4* p = (const float4*)(a + (size_t)r * HD);
    float s = 0.0f;
    #pragma unroll
    for (int i = 0; i < 16; i++) {
        float4 t = p[i];
        s = fmaf(t.x, t.x, s);
        s = fmaf(t.y, t.y, s);
        s = fmaf(t.z, t.z, s);
        s = fmaf(t.w, t.w, s);
    }
    o[r] = s;
}

// ---------------------------------------------------------------------------
// Flash attention with L2-distance scores:
//   s_ij = -sqrt(max(q2_i + k2_j - 2 q_i.k_j, 1e-12)); softmax over j; out = P V
// One block = one (b,h) pair x 64 query rows. 256 threads (16x16), 4x4
// micro-tiles for both S (64x64) and O (64 x hd=64).
// SMEM (dynamic, 66816 B): Qt[64][64] d-major, Kt[64][64] d-major,
// Vs[64][64] row-major, Pr[64][68] (padded, 16B-aligned), k2s[64].
// ---------------------------------------------------------------------------
#define ATT_SMEM_FLOATS (4096 * 3 + 64 * 68 + 64)
#define ATT_SMEM_BYTES  (ATT_SMEM_FLOATS * 4)

__global__ __launch_bounds__(256, 2)
void attn_kernel(const float* __restrict__ q, const float* __restrict__ k,
                 const float* __restrict__ v, const float* __restrict__ q2,
                 const float* __restrict__ k2, float* __restrict__ att)
{
    extern __shared__ float sm[];
    float* Qt  = sm;                      // [d][r]
    float* Kt  = sm + 4096;               // [d][c]
    float* Vs  = sm + 8192;               // [c][d]
    float* Pr  = sm + 12288;              // [r][68]
    float* k2s = sm + 12288 + 64 * 68;    // [64]

    const int tid = threadIdx.x;
    const int tx  = tid & 15;
    const int ty  = tid >> 4;
    const int r0  = ty * 4;
    const int c0  = tx * 4;
    const int bh  = blockIdx.y;           // b*H + h
    const int i0  = blockIdx.x * 64;
    const int bb  = bh >> 4;
    const int hh  = bh & 15;

    const float* qb = q + (size_t)bh * NN * HD;
    const float* kb = k + (size_t)bh * NN * HD;
    const float* vb = v + (size_t)bh * NN * HD;

    const int lrow = tid >> 2;            // 0..63
    const int lk   = (tid & 3) << 2;      // 0,4,8,12

    // Load Q tile transposed (once per block)
    #pragma unroll
    for (int dd = 0; dd < 64; dd += 16) {
        float4 a = *(const float4*)(qb + (size_t)(i0 + lrow) * HD + dd + lk);
        Qt[(dd + lk + 0) * 64 + lrow] = a.x;
        Qt[(dd + lk + 1) * 64 + lrow] = a.y;
        Qt[(dd + lk + 2) * 64 + lrow] = a.z;
        Qt[(dd + lk + 3) * 64 + lrow] = a.w;
    }

    float q2v[4];
    #pragma unroll
    for (int i = 0; i < 4; i++)
        q2v[i] = q2[(size_t)bh * NN + i0 + r0 + i];

    float mstate[4], lstate[4], O[4][4];
    #pragma unroll
    for (int i = 0; i < 4; i++) {
        mstate[i] = -1e30f;
        lstate[i] = 0.0f;
        #pragma unroll
        for (int j = 0; j < 4; j++) O[i][j] = 0.0f;
    }

    for (int j0 = 0; j0 < NN; j0 += 64) {
        __syncthreads();  // protect Kt/Vs from readers of previous iteration
        #pragma unroll
        for (int dd = 0; dd < 64; dd += 16) {
            float4 a = *(const float4*)(kb + (size_t)(j0 + lrow) * HD + dd + lk);
            Kt[(dd + lk + 0) * 64 + lrow] = a.x;
            Kt[(dd + lk + 1) * 64 + lrow] = a.y;
            Kt[(dd + lk + 2) * 64 + lrow] = a.z;
            Kt[(dd + lk + 3) * 64 + lrow] = a.w;
            float4 b2 = *(const float4*)(vb + (size_t)(j0 + lrow) * HD + dd + lk);
            *(float4*)&Vs[lrow * 64 + dd + lk] = b2;
        }
        if (tid < 64) k2s[tid] = k2[(size_t)bh * NN + j0 + tid];
        __syncthreads();

        // ---- S = Q K^T (4x4 per thread) ----
        float acc[4][4];
        #pragma unroll
        for (int i = 0; i < 4; i++)
            #pragma unroll
            for (int j = 0; j < 4; j++) acc[i][j] = 0.0f;

        #pragma unroll 16
        for (int d = 0; d < 64; d++) {
            float4 a = *(const float4*)&Qt[d * 64 + r0];
            float4 b = *(const float4*)&Kt[d * 64 + c0];
            float am[4] = {a.x, a.y, a.z, a.w};
            float bm[4] = {b.x, b.y, b.z, b.w};
            #pragma unroll
            for (int i = 0; i < 4; i++)
                #pragma unroll
                for (int j = 0; j < 4; j++)
                    acc[i][j] = fmaf(am[i], bm[j], acc[i][j]);
        }

        // ---- scores + online softmax ----
        float pv[4][4];
        #pragma unroll
        for (int i = 0; i < 4; i++)
            #pragma unroll
            for (int j = 0; j < 4; j++) {
                float d2 = q2v[i] + k2s[c0 + j] - 2.0f * acc[i][j];
                pv[i][j] = -sqrtf(fmaxf(d2, 1e-12f));
            }

        #pragma unroll
        for (int i = 0; i < 4; i++) {
            float rm = fmaxf(fmaxf(pv[i][0], pv[i][1]), fmaxf(pv[i][2], pv[i][3]));
            rm = fmaxf(rm, __shfl_xor_sync(0xffffffffu, rm, 1));
            rm = fmaxf(rm, __shfl_xor_sync(0xffffffffu, rm, 2));
            rm = fmaxf(rm, __shfl_xor_sync(0xffffffffu, rm, 4));
            rm = fmaxf(rm, __shfl_xor_sync(0xffffffffu, rm, 8));
            const float mn   = fmaxf(mstate[i], rm);
            const float corr = __expf(mstate[i] - mn);
            mstate[i] = mn;
            float rs = 0.0f;
            #pragma unroll
            for (int j = 0; j < 4; j++) {
                pv[i][j] = __expf(pv[i][j] - mn);
                rs += pv[i][j];
            }
            rs += __shfl_xor_sync(0xffffffffu, rs, 1);
            rs += __shfl_xor_sync(0xffffffffu, rs, 2);
            rs += __shfl_xor_sync(0xffffffffu, rs, 4);
            rs += __shfl_xor_sync(0xffffffffu, rs, 8);
            lstate[i] = lstate[i] * corr + rs;
            #pragma unroll
            for (int j = 0; j < 4; j++) O[i][j] *= corr;
            *(float4*)&Pr[(r0 + i) * 68 + c0] =
                make_float4(pv[i][0], pv[i][1], pv[i][2], pv[i][3]);
        }
        __syncthreads();  // Pr complete before PV reads it

        // ---- O += P V ----
        #pragma unroll 16
        for (int c = 0; c < 64; c++) {
            float a0 = Pr[(r0 + 0) * 68 + c];
            float a1 = Pr[(r0 + 1) * 68 + c];
            float a2 = Pr[(r0 + 2) * 68 + c];
            float a3 = Pr[(r0 + 3) * 68 + c];
            float4 b = *(const float4*)&Vs[c * 64 + c0];
            O[0][0] = fmaf(a0, b.x, O[0][0]);
            O[0][1] = fmaf(a0, b.y, O[0][1]);
            O[0][2] = fmaf(a0, b.z, O[0][2]);
            O[0][3] = fmaf(a0, b.w, O[0][3]);
            O[1][0] = fmaf(a1, b.x, O[1][0]);
            O[1][1] = fmaf(a1, b.y, O[1][1]);
            O[1][2] = fmaf(a1, b.z, O[1][2]);
            O[1][3] = fmaf(a1, b.w, O[1][3]);
            O[2][0] = fmaf(a2, b.x, O[2][0]);
            O[2][1] = fmaf(a2, b.y, O[2][1]);
            O[2][2] = fmaf(a2, b.z, O[2][2]);
            O[3][0] = fmaf(a3, b.x, O[3][0]);
            O[2][3] = fmaf(a2, b.w, O[2][3]);
            O[3][1] = fmaf(a3, b.y, O[3][1]);
            O[3][2] = fmaf(a3, b.z, O[3][2]);
            O[3][3] = fmaf(a3, b.w, O[3][3]);
        }
    }

    // Epilogue: normalize and write att (B*N, D) with column h*64 + d
    #pragma unroll
    for (int i = 0; i < 4; i++) {
        const float inv = 1.0f / lstate[i];
        const int m = bb * NN + i0 + r0 + i;
        float4 o = make_float4(O[i][0] * inv, O[i][1] * inv,
                               O[i][2] * inv, O[i][3] * inv);
        *(float4*)(att + (size_t)m * DD + hh * HD + c0) = o;
    }
}

// ---------------------------------------------------------------------------
// Launch
// ---------------------------------------------------------------------------
extern "C" void kernel_launch(void* const* d_in, const int* in_sizes, int n_in,
                              void* d_out, int out_size)
{
    (void)in_sizes; (void)n_in; (void)out_size;
    const float* x  = (const float*)d_in[0];
    const float* wq = (const float*)d_in[1];
    const float* bq = (const float*)d_in[2];
    const float* wk = (const float*)d_in[3];
    const float* bk = (const float*)d_in[4];
    const float* wv = (const float*)d_in[5];
    const float* bv = (const float*)d_in[6];
    const float* wo = (const float*)d_in[7];
    const float* bo = (const float*)d_in[8];
    float* out = (float*)d_out;

    float *qp, *kp, *vp, *q2p, *k2p, *ap;
    cudaGetSymbolAddress((void**)&qp,  g_q);
    cudaGetSymbolAddress((void**)&kp,  g_k);
    cudaGetSymbolAddress((void**)&vp,  g_v);
    cudaGetSymbolAddress((void**)&q2p, g_q2);
    cudaGetSymbolAddress((void**)&k2p, g_k2);
    cudaGetSymbolAddress((void**)&ap,  g_att);

    cudaFuncSetAttribute(attn_kernel,
                         cudaFuncAttributeMaxDynamicSharedMemorySize,
                         ATT_SMEM_BYTES);

    const dim3 gb(DD / 64, MM / 128);   // (16, 32)
    sgemm_kernel<1><<<gb, 256>>>(x, wq, bq, qp);
    sgemm_kernel<1><<<gb, 256>>>(x, wk, bk, kp);
    sgemm_kernel<1><<<gb, 256>>>(x, wv, bv, vp);

    rownorm_kernel<<<ROWS / 256, 256>>>(qp, q2p);
    rownorm_kernel<<<ROWS / 256, 256>>>(kp, k2p);

    attn_kernel<<<dim3(NN / 64, BB * HH), 256, ATT_SMEM_BYTES>>>(
        qp, kp, vp, q2p, k2p, ap);

    sgemm_kernel<0><<<gb, 256>>>(ap, wo, bo, out);
}

// round 12
// speedup vs baseline: 1.1066x; 1.1066x over previous
#include <cuda_runtime.h>
#include <math.h>

// Problem constants (fixed by the reference: B=2, N=2048, D=1024, H=16, hd=64)
#define BB   2
#define NN   2048
#define DD   1024
#define HH   16
#define HD   64
#define MM   (BB * NN)        // 4096 total tokens
#define ROWS (BB * HH * NN)   // 65536 (b,h,n) rows of length 64

// Scratch: device globals (no allocations allowed)
__device__ float g_q[ROWS * HD];     // (B,H,N,hd)
__device__ float g_k[ROWS * HD];
__device__ float g_v[ROWS * HD];
__device__ float g_q2[ROWS];         // |q|^2 per row
__device__ float g_k2[ROWS];
__device__ float g_att[MM * DD];     // attention output, (B*N, D) with D = H*hd

// ---------------------------------------------------------------------------
// SGEMM: C[m][c] = sum_k A[m][k] * W[c][k] + bias[c]
// A: (M,1024) row-major, W: (1024,1024) row-major (A @ W^T).
// Tile: BM=128, BN=128, BK=16; 256 threads; 8x8 micro-tile; double-buffered
// SMEM with register prefetch of the next global tile during compute.
// MODE 0: C is (M,1024) row-major.
// MODE 1: C is head layout (B,H,N,hd); each 64-col half of the 128-col tile
//         is one head.
// ---------------------------------------------------------------------------
template <int MODE>
__global__ __launch_bounds__(256, 2)
void sgemm_kernel(const float* __restrict__ A, const float* __restrict__ W,
                  const float* __restrict__ bias, float* __restrict__ C)
{
    __shared__ float As[2][16][128];   // [buf][k][m]
    __shared__ float Bs[2][16][128];   // [buf][k][n]

    const int tid = threadIdx.x;
    const int tx  = tid & 15;          // n micro-col group (8 cols)
    const int ty  = tid >> 4;          // m micro-row group (8 rows)
    const int m0  = blockIdx.y * 128;
    const int n0  = blockIdx.x * 128;

    const int trow = tid >> 1;         // 0..127
    const int tk   = (tid & 1) * 8;    // 0 or 8

    const float* Ap = A + (size_t)(m0 + trow) * DD + tk;
    const float* Wp = W + (size_t)(n0 + trow) * DD + tk;

    float acc[8][8];
    #pragma unroll
    for (int i = 0; i < 8; i++)
        #pragma unroll
        for (int j = 0; j < 8; j++) acc[i][j] = 0.0f;

    // ---- prologue: load first k-tile into buffer 0 ----
    {
        float4 a0 = *(const float4*)(Ap);
        float4 a1 = *(const float4*)(Ap + 4);
        float4 b0 = *(const float4*)(Wp);
        float4 b1 = *(const float4*)(Wp + 4);
        As[0][tk + 0][trow] = a0.x; As[0][tk + 1][trow] = a0.y;
        As[0][tk + 2][trow] = a0.z; As[0][tk + 3][trow] = a0.w;
        As[0][tk + 4][trow] = a1.x; As[0][tk + 5][trow] = a1.y;
        As[0][tk + 6][trow] = a1.z; As[0][tk + 7][trow] = a1.w;
        Bs[0][tk + 0][trow] = b0.x; Bs[0][tk + 1][trow] = b0.y;
        Bs[0][tk + 2][trow] = b0.z; Bs[0][tk + 3][trow] = b0.w;
        Bs[0][tk + 4][trow] = b1.x; Bs[0][tk + 5][trow] = b1.y;
        Bs[0][tk + 6][trow] = b1.z; Bs[0][tk + 7][trow] = b1.w;
    }
    __syncthreads();

    int cur = 0;
    #pragma unroll 1
    for (int k0 = 0; k0 < DD; k0 += 16) {
        const bool hasnext = (k0 + 16 < DD);
        float4 na0, na1, nb0, nb1;
        if (hasnext) {
            na0 = *(const float4*)(Ap + k0 + 16);
            na1 = *(const float4*)(Ap + k0 + 20);
            nb0 = *(const float4*)(Wp + k0 + 16);
            nb1 = *(const float4*)(Wp + k0 + 20);
        }

        #pragma unroll
        for (int kk = 0; kk < 16; kk++) {
            float4 af0 = *(const float4*)&As[cur][kk][ty * 8];
            float4 af1 = *(const float4*)&As[cur][kk][ty * 8 + 4];
            float4 bf0 = *(const float4*)&Bs[cur][kk][tx * 8];
            float4 bf1 = *(const float4*)&Bs[cur][kk][tx * 8 + 4];
            float am[8] = {af0.x, af0.y, af0.z, af0.w, af1.x, af1.y, af1.z, af1.w};
            float bm[8] = {bf0.x, bf0.y, bf0.z, bf0.w, bf1.x, bf1.y, bf1.z, bf1.w};
            #pragma unroll
            for (int i = 0; i < 8; i++)
                #pragma unroll
                for (int j = 0; j < 8; j++)
                    acc[i][j] = fmaf(am[i], bm[j], acc[i][j]);
        }

        if (hasnext) {
            cur ^= 1;   // safe: others only read the buffer we just computed on
            As[cur][tk + 0][trow] = na0.x; As[cur][tk + 1][trow] = na0.y;
            As[cur][tk + 2][trow] = na0.z; As[cur][tk + 3][trow] = na0.w;
            As[cur][tk + 4][trow] = na1.x; As[cur][tk + 5][trow] = na1.y;
            As[cur][tk + 6][trow] = na1.z; As[cur][tk + 7][trow] = na1.w;
            Bs[cur][tk + 0][trow] = nb0.x; Bs[cur][tk + 1][trow] = nb0.y;
            Bs[cur][tk + 2][trow] = nb0.z; Bs[cur][tk + 3][trow] = nb0.w;
            Bs[cur][tk + 4][trow] = nb1.x; Bs[cur][tk + 5][trow] = nb1.y;
            Bs[cur][tk + 6][trow] = nb1.z; Bs[cur][tk + 7][trow] = nb1.w;
            __syncthreads();
        }
    }

    // ---- epilogue ----
    const int ncol = n0 + tx * 8;
    const float4 bv0 = *(const float4*)(bias + ncol);
    const float4 bv1 = *(const float4*)(bias + ncol + 4);
    #pragma unroll
    for (int i = 0; i < 8; i++) {
        const int m = m0 + ty * 8 + i;
        float4 o0, o1;
        o0.x = acc[i][0] + bv0.x; o0.y = acc[i][1] + bv0.y;
        o0.z = acc[i][2] + bv0.z; o0.w = acc[i][3] + bv0.w;
        o1.x = acc[i][4] + bv1.x; o1.y = acc[i][5] + bv1.y;
        o1.z = acc[i][6] + bv1.z; o1.w = acc[i][7] + bv1.w;
        if (MODE == 0) {
            *(float4*)(C + (size_t)m * DD + ncol)     = o0;
            *(float4*)(C + (size_t)m * DD + ncol + 4) = o1;
        } else {
            const int b = m >> 11;          // m / 2048
            const int n = m & 2047;
            const int h = ncol >> 6;
            const int d = ncol & 63;        // 8-aligned, stays within one head
            float* base = C + (((size_t)(b * HH + h)) * NN + n) * HD + d;
            *(float4*)(base)     = o0;
            *(float4*)(base + 4) = o1;
        }
    }
}

// ---------------------------------------------------------------------------
// Row squared-norm over the last dim (64) of (B,H,N,hd)
// ---------------------------------------------------------------------------
__global__ __launch_bounds__(256)
void rownorm_kernel(const float* __restrict__ a, float* __restrict__ o)
{
    const int r = blockIdx.x * blockDim.x + threadIdx.x;
    if (r >= ROWS) return;
    const float4* p = (const float4*)(a + (size_t)r * HD);
    float s = 0.0f;
    #pragma unroll
    for (int i = 0; i < 16; i++) {
        float4 t = p[i];
        s = fmaf(t.x, t.x, s);
        s = fmaf(t.y, t.y, s);
        s = fmaf(t.z, t.z, s);
        s = fmaf(t.w, t.w, s);
    }
    o[r] = s;
}

// ---------------------------------------------------------------------------
// Flash attention with L2-distance scores, NO online max:
//   s_ij = -sqrt(max(q2_i + k2_j - 2 q_i.k_j, 1e-12)) <= 0
//   => exp(s_ij) in (0,1]: no overflow possible, so softmax is computed
//      directly (P = exp(s), l = sum P, O = P V / l) with no max tracking,
//      no rescaling, no per-tile shuffle reductions.
// One block = one (b,h) pair x 64 query rows. 256 threads (16x16), 4x4
// micro-tiles for S (64x64) and O (64x64).
// ---------------------------------------------------------------------------
#define ATT_SMEM_FLOATS (4096 * 3 + 64 * 68 + 64)
#define ATT_SMEM_BYTES  (ATT_SMEM_FLOATS * 4)

__global__ __launch_bounds__(256, 2)
void attn_kernel(const float* __restrict__ q, const float* __restrict__ k,
                 const float* __restrict__ v, const float* __restrict__ q2,
                 const float* __restrict__ k2, float* __restrict__ att)
{
    extern __shared__ float sm[];
    float* Qt  = sm;                      // [d][r]
    float* Kt  = sm + 4096;               // [d][c]
    float* Vs  = sm + 8192;               // [c][d]
    float* Pr  = sm + 12288;              // [r][68] padded
    float* k2s = sm + 12288 + 64 * 68;    // [64]

    const int tid = threadIdx.x;
    const int tx  = tid & 15;
    const int ty  = tid >> 4;
    const int r0  = ty * 4;
    const int c0  = tx * 4;
    const int bh  = blockIdx.y;           // b*H + h
    const int i0  = blockIdx.x * 64;
    const int bb  = bh >> 4;
    const int hh  = bh & 15;

    const float* qb = q + (size_t)bh * NN * HD;
    const float* kb = k + (size_t)bh * NN * HD;
    const float* vb = v + (size_t)bh * NN * HD;

    const int lrow = tid >> 2;            // 0..63
    const int lk   = (tid & 3) << 2;      // 0,4,8,12

    // Load Q tile transposed (once per block)
    #pragma unroll
    for (int dd = 0; dd < 64; dd += 16) {
        float4 a = *(const float4*)(qb + (size_t)(i0 + lrow) * HD + dd + lk);
        Qt[(dd + lk + 0) * 64 + lrow] = a.x;
        Qt[(dd + lk + 1) * 64 + lrow] = a.y;
        Qt[(dd + lk + 2) * 64 + lrow] = a.z;
        Qt[(dd + lk + 3) * 64 + lrow] = a.w;
    }

    float q2v[4];
    #pragma unroll
    for (int i = 0; i < 4; i++)
        q2v[i] = q2[(size_t)bh * NN + i0 + r0 + i];

    float lsum[4], O[4][4];
    #pragma unroll
    for (int i = 0; i < 4; i++) {
        lsum[i] = 0.0f;
        #pragma unroll
        for (int j = 0; j < 4; j++) O[i][j] = 0.0f;
    }

    #pragma unroll 1
    for (int j0 = 0; j0 < NN; j0 += 64) {
        __syncthreads();  // protect Kt/Vs/Pr from readers of previous iter
        #pragma unroll
        for (int dd = 0; dd < 64; dd += 16) {
            float4 a = *(const float4*)(kb + (size_t)(j0 + lrow) * HD + dd + lk);
            Kt[(dd + lk + 0) * 64 + lrow] = a.x;
            Kt[(dd + lk + 1) * 64 + lrow] = a.y;
            Kt[(dd + lk + 2) * 64 + lrow] = a.z;
            Kt[(dd + lk + 3) * 64 + lrow] = a.w;
            float4 b2 = *(const float4*)(vb + (size_t)(j0 + lrow) * HD + dd + lk);
            *(float4*)&Vs[lrow * 64 + dd + lk] = b2;
        }
        if (tid < 64) k2s[tid] = k2[(size_t)bh * NN + j0 + tid];
        __syncthreads();

        // ---- S = Q K^T (4x4 per thread) ----
        float acc[4][4];
        #pragma unroll
        for (int i = 0; i < 4; i++)
            #pragma unroll
            for (int j = 0; j < 4; j++) acc[i][j] = 0.0f;

        #pragma unroll 16
        for (int d = 0; d < 64; d++) {
            float4 a = *(const float4*)&Qt[d * 64 + r0];
            float4 b = *(const float4*)&Kt[d * 64 + c0];
            float am[4] = {a.x, a.y, a.z, a.w};
            float bm[4] = {b.x, b.y, b.z, b.w};
            #pragma unroll
            for (int i = 0; i < 4; i++)
                #pragma unroll
                for (int j = 0; j < 4; j++)
                    acc[i][j] = fmaf(am[i], bm[j], acc[i][j]);
        }

        // ---- P = exp(-sqrt(d2)), direct (max = 0) ----
        const float4 kq = *(const float4*)&k2s[c0];
        const float k2r[4] = {kq.x, kq.y, kq.z, kq.w};
        #pragma unroll
        for (int i = 0; i < 4; i++) {
            float pv[4];
            #pragma unroll
            for (int j = 0; j < 4; j++) {
                float d2 = fmaxf(fmaf(acc[i][j], -2.0f, q2v[i] + k2r[j]), 1e-12f);
                float s  = d2 * rsqrtf(d2);      // sqrt via MUFU.RSQ + mul
                pv[j] = __expf(-s);
            }
            lsum[i] += (pv[0] + pv[1]) + (pv[2] + pv[3]);
            *(float4*)&Pr[(r0 + i) * 68 + c0] =
                make_float4(pv[0], pv[1], pv[2], pv[3]);
        }
        __syncthreads();  // Pr complete before PV reads it

        // ---- O += P V ----
        #pragma unroll 16
        for (int c = 0; c < 64; c++) {
            float a0 = Pr[(r0 + 0) * 68 + c];
            float a1 = Pr[(r0 + 1) * 68 + c];
            float a2 = Pr[(r0 + 2) * 68 + c];
            float a3 = Pr[(r0 + 3) * 68 + c];
            float4 b = *(const float4*)&Vs[c * 64 + c0];
            O[0][0] = fmaf(a0, b.x, O[0][0]);
            O[0][1] = fmaf(a0, b.y, O[0][1]);
            O[0][2] = fmaf(a0, b.z, O[0][2]);
            O[0][3] = fmaf(a0, b.w, O[0][3]);
            O[1][0] = fmaf(a1, b.x, O[1][0]);
            O[1][1] = fmaf(a1, b.y, O[1][1]);
            O[1][2] = fmaf(a1, b.z, O[1][2]);
            O[1][3] = fmaf(a1, b.w, O[1][3]);
            O[2][0] = fmaf(a2, b.x, O[2][0]);
            O[2][1] = fmaf(a2, b.y, O[2][1]);
            O[2][2] = fmaf(a2, b.z, O[2][2]);
            O[2][3] = fmaf(a2, b.w, O[2][3]);
            O[3][0] = fmaf(a3, b.x, O[3][0]);
            O[3][1] = fmaf(a3, b.y, O[3][1]);
            O[3][2] = fmaf(a3, b.z, O[3][2]);
            O[3][3] = fmaf(a3, b.w, O[3][3]);
        }
    }

    // Epilogue: single row-sum reduction across the 16 tx lanes, then write.
    #pragma unroll
    for (int i = 0; i < 4; i++) {
        float l = lsum[i];
        l += __shfl_xor_sync(0xffffffffu, l, 1);
        l += __shfl_xor_sync(0xffffffffu, l, 2);
        l += __shfl_xor_sync(0xffffffffu, l, 4);
        l += __shfl_xor_sync(0xffffffffu, l, 8);
        const float inv = 1.0f / l;
        const int m = bb * NN + i0 + r0 + i;
        float4 o = make_float4(O[i][0] * inv, O[i][1] * inv,
                               O[i][2] * inv, O[i][3] * inv);
        *(float4*)(att + (size_t)m * DD + hh * HD + c0) = o;
    }
}

// ---------------------------------------------------------------------------
// Launch
// ---------------------------------------------------------------------------
extern "C" void kernel_launch(void* const* d_in, const int* in_sizes, int n_in,
                              void* d_out, int out_size)
{
    (void)in_sizes; (void)n_in; (void)out_size;
    const float* x  = (const float*)d_in[0];
    const float* wq = (const float*)d_in[1];
    const float* bq = (const float*)d_in[2];
    const float* wk = (const float*)d_in[3];
    const float* bk = (const float*)d_in[4];
    const float* wv = (const float*)d_in[5];
    const float* bv = (const float*)d_in[6];
    const float* wo = (const float*)d_in[7];
    const float* bo = (const float*)d_in[8];
    float* out = (float*)d_out;

    float *qp, *kp, *vp, *q2p, *k2p, *ap;
    cudaGetSymbolAddress((void**)&qp,  g_q);
    cudaGetSymbolAddress((void**)&kp,  g_k);
    cudaGetSymbolAddress((void**)&vp,  g_v);
    cudaGetSymbolAddress((void**)&q2p, g_q2);
    cudaGetSymbolAddress((void**)&k2p, g_k2);
    cudaGetSymbolAddress((void**)&ap,  g_att);

    cudaFuncSetAttribute(attn_kernel,
                         cudaFuncAttributeMaxDynamicSharedMemorySize,
                         ATT_SMEM_BYTES);

    const dim3 gb(DD / 128, MM / 128);   // (8, 32)
    sgemm_kernel<1><<<gb, 256>>>(x, wq, bq, qp);
    sgemm_kernel<1><<<gb, 256>>>(x, wk, bk, kp);
    sgemm_kernel<1><<<gb, 256>>>(x, wv, bv, vp);

    rownorm_kernel<<<ROWS / 256, 256>>>(qp, q2p);
    rownorm_kernel<<<ROWS / 256, 256>>>(kp, k2p);

    attn_kernel<<<dim3(NN / 64, BB * HH), 256, ATT_SMEM_BYTES>>>(
        qp, kp, vp, q2p, k2p, ap);

    sgemm_kernel<0><<<gb, 256>>>(ap, wo, bo, out);
}

// round 14
// speedup vs baseline: 1.5246x; 1.3777x over previous
#include <cuda_runtime.h>
#include <cuda_bf16.h>
#include <math.h>
#include <stdint.h>

// Problem constants (B=2, N=2048, D=1024, H=16, hd=64)
#define BB   2
#define NN   2048
#define DD   1024
#define HH   16
#define HD   64
#define MM   (BB * NN)        // 4096 tokens
#define ROWS (BB * HH * NN)   // 65536

// Scratch device globals (no allocations allowed)
__device__ float g_q[ROWS * HD];
__device__ float g_k[ROWS * HD];
__device__ float g_v[ROWS * HD];
__device__ float g_q2[ROWS];
__device__ float g_k2[ROWS];
__device__ float g_att[MM * DD];

// ===========================================================================
// Helpers (baseline PTX only — sm_80-era mma.sync / ldmatrix, valid on
// compute_103 base target; NO tcgen05 / a-suffix features)
// ===========================================================================
__device__ __forceinline__ uint32_t smem_u32(const void* p) {
    uint32_t a;
    asm("{ .reg .u64 t; cvta.to.shared.u64 t, %1; cvt.u32.u64 %0, t; }"
        : "=r"(a) : "l"(p));
    return a;
}

__device__ __forceinline__ void ldx4(uint32_t* r, uint32_t addr) {
    asm volatile("ldmatrix.sync.aligned.m8n8.x4.shared.b16 {%0,%1,%2,%3}, [%4];"
                 : "=r"(r[0]), "=r"(r[1]), "=r"(r[2]), "=r"(r[3]) : "r"(addr));
}

__device__ __forceinline__ void mma16816(float* c, const uint32_t* a,
                                         uint32_t b0, uint32_t b1) {
    asm volatile(
        "mma.sync.aligned.m16n8k16.row.col.f32.bf16.bf16.f32 "
        "{%0,%1,%2,%3}, {%4,%5,%6,%7}, {%8,%9}, {%0,%1,%2,%3};"
        : "+f"(c[0]), "+f"(c[1]), "+f"(c[2]), "+f"(c[3])
        : "r"(a[0]), "r"(a[1]), "r"(a[2]), "r"(a[3]), "r"(b0), "r"(b1));
}

// fp32 -> (hi bf16 = truncation, lo bf16 = rn(x - hi)), packed pairs
__device__ __forceinline__ void split4(float4 f, uint32_t& h01, uint32_t& h23,
                                       uint32_t& l01, uint32_t& l23) {
    uint32_t bx = __float_as_uint(f.x), by = __float_as_uint(f.y);
    uint32_t bz = __float_as_uint(f.z), bw = __float_as_uint(f.w);
    h01 = __byte_perm(bx, by, 0x7632);   // lo half = bf16(x), hi half = bf16(y)
    h23 = __byte_perm(bz, bw, 0x7632);
    float lx = f.x - __uint_as_float(bx & 0xFFFF0000u);
    float ly = f.y - __uint_as_float(by & 0xFFFF0000u);
    float lz = f.z - __uint_as_float(bz & 0xFFFF0000u);
    float lw = f.w - __uint_as_float(bw & 0xFFFF0000u);
    asm("cvt.rn.bf16x2.f32 %0, %1, %2;" : "=r"(l01) : "f"(ly), "f"(lx));
    asm("cvt.rn.bf16x2.f32 %0, %1, %2;" : "=r"(l23) : "f"(lw), "f"(lz));
}

// ===========================================================================
// Split-bf16 tensor-core GEMM: C[m][c] = sum_k A[m][k]*W[c][k] + bias[c]
// CTA tile 128x64, BK=32 fp32 elems/chunk, 256 threads (8 warps, 4m x 2n),
// warp tile 32x32 (2 m16 x 4 n8 mma tiles), 3 passes (AhWh + AhWl + AlWh).
// SMEM: double-buffered hi/lo bf16 planes, row stride 80 B (40 halves) =>
// conflict-free ldmatrix. Register prefetch of next chunk overlaps MMA.
// MODE 0: C row-major (M,1024). MODE 1: head layout (B,H,N,hd); BN=64 = one
// head per CTA.
// ===========================================================================
#define LDP   80                    // bytes per SMEM plane row
#define P_AH  0
#define P_AL  10240                 // 128*80
#define P_BH  20480
#define P_BL  25600                 // + 64*80
#define BUF_BYTES 30720
#define GEMM_SMEM (2 * BUF_BYTES)   // 61440

template <int MODE>
__global__ __launch_bounds__(256, 2)
void wg_gemm(const float* __restrict__ A, const float* __restrict__ W,
             const float* __restrict__ bias, float* __restrict__ C)
{
    extern __shared__ char smc[];
    const uint32_t sb = smem_u32(smc);
    const int tid = threadIdx.x;
    const int wid = tid >> 5;
    const int lid = tid & 31;
    const int wm  = wid & 3;          // warp m index (4)
    const int wn  = wid >> 2;         // warp n index (2)
    const int m0  = blockIdx.y * 128;
    const int n0  = blockIdx.x * 64;

    // staging: each thread owns rows (tid>>3)+32i, float4 #(tid&7) of 32 floats
    const int arow = tid >> 3;        // 0..31
    const int aq   = tid & 7;
    const float* Abase = A + (size_t)(m0 + arow) * DD + aq * 4;
    const float* Wbase = W + (size_t)(n0 + arow) * DD + aq * 4;
    const uint32_t soff = (uint32_t)(arow * LDP + aq * 8);

    float acc[2][4][4];
    #pragma unroll
    for (int mb = 0; mb < 2; mb++)
        #pragma unroll
        for (int nt = 0; nt < 4; nt++)
            #pragma unroll
            for (int e = 0; e < 4; e++) acc[mb][nt][e] = 0.0f;

    float4 pa[4], pb[2];
    // ---- prologue: load + stage chunk 0 ----
    #pragma unroll
    for (int i = 0; i < 4; i++) pa[i] = *(const float4*)(Abase + (size_t)i * 32 * DD);
    #pragma unroll
    for (int i = 0; i < 2; i++) pb[i] = *(const float4*)(Wbase + (size_t)i * 32 * DD);
    {
        const uint32_t bufb = sb;
        #pragma unroll
        for (int i = 0; i < 4; i++) {
            uint32_t h01, h23, l01, l23;
            split4(pa[i], h01, h23, l01, l23);
            asm volatile("st.shared.v2.b32 [%0], {%1, %2};"
                         :: "r"(bufb + P_AH + soff + i * 32 * LDP), "r"(h01), "r"(h23) : "memory");
            asm volatile("st.shared.v2.b32 [%0], {%1, %2};"
                         :: "r"(bufb + P_AL + soff + i * 32 * LDP), "r"(l01), "r"(l23) : "memory");
        }
        #pragma unroll
        for (int i = 0; i < 2; i++) {
            uint32_t h01, h23, l01, l23;
            split4(pb[i], h01, h23, l01, l23);
            asm volatile("st.shared.v2.b32 [%0], {%1, %2};"
                         :: "r"(bufb + P_BH + soff + i * 32 * LDP), "r"(h01), "r"(h23) : "memory");
            asm volatile("st.shared.v2.b32 [%0], {%1, %2};"
                         :: "r"(bufb + P_BL + soff + i * 32 * LDP), "r"(l01), "r"(l23) : "memory");
        }
    }
    __syncthreads();

    #pragma unroll 1
    for (int c = 0; c < 32; c++) {
        const uint32_t bufb = sb + (uint32_t)(c & 1) * BUF_BYTES;
        const bool hasnext = (c + 1 < 32);
        if (hasnext) {
            const int k0 = (c + 1) * 32;
            #pragma unroll
            for (int i = 0; i < 4; i++)
                pa[i] = *(const float4*)(Abase + (size_t)i * 32 * DD + k0);
            #pragma unroll
            for (int i = 0; i < 2; i++)
                pb[i] = *(const float4*)(Wbase + (size_t)i * 32 * DD + k0);
        }

        // ---- MMA on current buffer ----
        #pragma unroll
        for (int kb = 0; kb < 2; kb++) {
            const uint32_t lmrow = (uint32_t)(lid & 15) * LDP;
            const uint32_t lmcol = (uint32_t)(kb * 32 + (lid >> 4) * 16);
            const uint32_t aA = bufb + P_AH + (uint32_t)(wm * 32) * LDP + lmrow + lmcol;
            const uint32_t aB = bufb + P_BH + (uint32_t)(wn * 32) * LDP + lmrow + lmcol;
            uint32_t ah[2][4], al[2][4], bh[2][4], bl[2][4];
            ldx4(ah[0], aA);
            ldx4(ah[1], aA + 16 * LDP);
            ldx4(al[0], aA + (P_AL - P_AH));
            ldx4(al[1], aA + (P_AL - P_AH) + 16 * LDP);
            ldx4(bh[0], aB);
            ldx4(bh[1], aB + 16 * LDP);
            ldx4(bl[0], aB + (P_BL - P_BH));
            ldx4(bl[1], aB + (P_BL - P_BH) + 16 * LDP);
            #pragma unroll
            for (int mb = 0; mb < 2; mb++)
                #pragma unroll
                for (int nt = 0; nt < 4; nt++) {
                    const int nb = nt >> 1, s = nt & 1;
                    mma16816(acc[mb][nt], ah[mb], bh[nb][s], bh[nb][2 + s]);
                    mma16816(acc[mb][nt], ah[mb], bl[nb][s], bl[nb][2 + s]);
                    mma16816(acc[mb][nt], al[mb], bh[nb][s], bh[nb][2 + s]);
                }
        }

        // ---- stage next chunk into the other buffer ----
        if (hasnext) {
            const uint32_t nb2 = sb + (uint32_t)((c + 1) & 1) * BUF_BYTES;
            #pragma unroll
            for (int i = 0; i < 4; i++) {
                uint32_t h01, h23, l01, l23;
                split4(pa[i], h01, h23, l01, l23);
                asm volatile("st.shared.v2.b32 [%0], {%1, %2};"
                             :: "r"(nb2 + P_AH + soff + i * 32 * LDP), "r"(h01), "r"(h23) : "memory");
                asm volatile("st.shared.v2.b32 [%0], {%1, %2};"
                             :: "r"(nb2 + P_AL + soff + i * 32 * LDP), "r"(l01), "r"(l23) : "memory");
            }
            #pragma unroll
            for (int i = 0; i < 2; i++) {
                uint32_t h01, h23, l01, l23;
                split4(pb[i], h01, h23, l01, l23);
                asm volatile("st.shared.v2.b32 [%0], {%1, %2};"
                             :: "r"(nb2 + P_BH + soff + i * 32 * LDP), "r"(h01), "r"(h23) : "memory");
                asm volatile("st.shared.v2.b32 [%0], {%1, %2};"
                             :: "r"(nb2 + P_BL + soff + i * 32 * LDP), "r"(l01), "r"(l23) : "memory");
            }
        }
        __syncthreads();
    }

    // ---- epilogue ----
    const int gid = lid >> 2;      // 0..7
    const int tig = lid & 3;       // 0..3
    #pragma unroll
    for (int mb = 0; mb < 2; mb++) {
        #pragma unroll
        for (int nt = 0; nt < 4; nt++) {
            const int col  = wn * 32 + nt * 8 + tig * 2;  // 0..62 within CTA
            const int gcol = n0 + col;
            const float bx = bias[gcol];
            const float by = bias[gcol + 1];
            const int row0 = m0 + wm * 32 + mb * 16 + gid;
            const int row1 = row0 + 8;
            float2 o0 = make_float2(acc[mb][nt][0] + bx, acc[mb][nt][1] + by);
            float2 o1 = make_float2(acc[mb][nt][2] + bx, acc[mb][nt][3] + by);
            if (MODE == 0) {
                *(float2*)(C + (size_t)row0 * DD + gcol) = o0;
                *(float2*)(C + (size_t)row1 * DD + gcol) = o1;
            } else {
                const int h = n0 >> 6;
                const int b0i = row0 >> 11, n0i = row0 & 2047;
                const int b1i = row1 >> 11, n1i = row1 & 2047;
                *(float2*)(C + (((size_t)(b0i * HH + h)) * NN + n0i) * HD + col) = o0;
                *(float2*)(C + (((size_t)(b1i * HH + h)) * NN + n1i) * HD + col) = o1;
            }
        }
    }
}

// ---------------------------------------------------------------------------
// Row squared-norm over the last dim (64) of (B,H,N,hd)
// ---------------------------------------------------------------------------
__global__ __launch_bounds__(256)
void rownorm_kernel(const float* __restrict__ a, float* __restrict__ o)
{
    const int r = blockIdx.x * blockDim.x + threadIdx.x;
    if (r >= ROWS) return;
    const float4* p = (const float4*)(a + (size_t)r * HD);
    float s = 0.0f;
    #pragma unroll
    for (int i = 0; i < 16; i++) {
        float4 t = p[i];
        s = fmaf(t.x, t.x, s);
        s = fmaf(t.y, t.y, s);
        s = fmaf(t.z, t.z, s);
        s = fmaf(t.w, t.w, s);
    }
    o[r] = s;
}

// ---------------------------------------------------------------------------
// Flash attention with L2-distance scores, no max subtraction (scores <= 0).
// ---------------------------------------------------------------------------
#define ATT_SMEM_FLOATS (4096 * 3 + 64 * 68 + 64)
#define ATT_SMEM_BYTES  (ATT_SMEM_FLOATS * 4)

__global__ __launch_bounds__(256, 2)
void attn_kernel(const float* __restrict__ q, const float* __restrict__ k,
                 const float* __restrict__ v, const float* __restrict__ q2,
                 const float* __restrict__ k2, float* __restrict__ att)
{
    extern __shared__ float sm[];
    float* Qt  = sm;
    float* Kt  = sm + 4096;
    float* Vs  = sm + 8192;
    float* Pr  = sm + 12288;
    float* k2s = sm + 12288 + 64 * 68;

    const int tid = threadIdx.x;
    const int tx  = tid & 15;
    const int ty  = tid >> 4;
    const int r0  = ty * 4;
    const int c0  = tx * 4;
    const int bh  = blockIdx.y;
    const int i0  = blockIdx.x * 64;
    const int bb  = bh >> 4;
    const int hh  = bh & 15;

    const float* qb = q + (size_t)bh * NN * HD;
    const float* kb = k + (size_t)bh * NN * HD;
    const float* vb = v + (size_t)bh * NN * HD;

    const int lrow = tid >> 2;
    const int lk   = (tid & 3) << 2;

    #pragma unroll
    for (int dd = 0; dd < 64; dd += 16) {
        float4 a = *(const float4*)(qb + (size_t)(i0 + lrow) * HD + dd + lk);
        Qt[(dd + lk + 0) * 64 + lrow] = a.x;
        Qt[(dd + lk + 1) * 64 + lrow] = a.y;
        Qt[(dd + lk + 2) * 64 + lrow] = a.z;
        Qt[(dd + lk + 3) * 64 + lrow] = a.w;
    }

    float q2v[4];
    #pragma unroll
    for (int i = 0; i < 4; i++)
        q2v[i] = q2[(size_t)bh * NN + i0 + r0 + i];

    float lsum[4], O[4][4];
    #pragma unroll
    for (int i = 0; i < 4; i++) {
        lsum[i] = 0.0f;
        #pragma unroll
        for (int j = 0; j < 4; j++) O[i][j] = 0.0f;
    }

    #pragma unroll 1
    for (int j0 = 0; j0 < NN; j0 += 64) {
        __syncthreads();
        #pragma unroll
        for (int dd = 0; dd < 64; dd += 16) {
            float4 a = *(const float4*)(kb + (size_t)(j0 + lrow) * HD + dd + lk);
            Kt[(dd + lk + 0) * 64 + lrow] = a.x;
            Kt[(dd + lk + 1) * 64 + lrow] = a.y;
            Kt[(dd + lk + 2) * 64 + lrow] = a.z;
            Kt[(dd + lk + 3) * 64 + lrow] = a.w;
            float4 b2 = *(const float4*)(vb + (size_t)(j0 + lrow) * HD + dd + lk);
            *(float4*)&Vs[lrow * 64 + dd + lk] = b2;
        }
        if (tid < 64) k2s[tid] = k2[(size_t)bh * NN + j0 + tid];
        __syncthreads();

        float acc[4][4];
        #pragma unroll
        for (int i = 0; i < 4; i++)
            #pragma unroll
            for (int j = 0; j < 4; j++) acc[i][j] = 0.0f;

        #pragma unroll 16
        for (int d = 0; d < 64; d++) {
            float4 a = *(const float4*)&Qt[d * 64 + r0];
            float4 b = *(const float4*)&Kt[d * 64 + c0];
            float am[4] = {a.x, a.y, a.z, a.w};
            float bm[4] = {b.x, b.y, b.z, b.w};
            #pragma unroll
            for (int i = 0; i < 4; i++)
                #pragma unroll
                for (int j = 0; j < 4; j++)
                    acc[i][j] = fmaf(am[i], bm[j], acc[i][j]);
        }

        const float4 kq = *(const float4*)&k2s[c0];
        const float k2r[4] = {kq.x, kq.y, kq.z, kq.w};
        #pragma unroll
        for (int i = 0; i < 4; i++) {
            float pv[4];
            #pragma unroll
            for (int j = 0; j < 4; j++) {
                float d2 = fmaxf(fmaf(acc[i][j], -2.0f, q2v[i] + k2r[j]), 1e-12f);
                float s  = d2 * rsqrtf(d2);
                pv[j] = __expf(-s);
            }
            lsum[i] += (pv[0] + pv[1]) + (pv[2] + pv[3]);
            *(float4*)&Pr[(r0 + i) * 68 + c0] =
                make_float4(pv[0], pv[1], pv[2], pv[3]);
        }
        __syncthreads();

        #pragma unroll 16
        for (int c = 0; c < 64; c++) {
            float a0 = Pr[(r0 + 0) * 68 + c];
            float a1 = Pr[(r0 + 1) * 68 + c];
            float a2 = Pr[(r0 + 2) * 68 + c];
            float a3 = Pr[(r0 + 3) * 68 + c];
            float4 b = *(const float4*)&Vs[c * 64 + c0];
            O[0][0] = fmaf(a0, b.x, O[0][0]);
            O[0][1] = fmaf(a0, b.y, O[0][1]);
            O[0][2] = fmaf(a0, b.z, O[0][2]);
            O[0][3] = fmaf(a0, b.w, O[0][3]);
            O[1][0] = fmaf(a1, b.x, O[1][0]);
            O[1][1] = fmaf(a1, b.y, O[1][1]);
            O[1][2] = fmaf(a1, b.z, O[1][2]);
            O[1][3] = fmaf(a1, b.w, O[1][3]);
            O[2][0] = fmaf(a2, b.x, O[2][0]);
            O[2][1] = fmaf(a2, b.y, O[2][1]);
            O[2][2] = fmaf(a2, b.z, O[2][2]);
            O[2][3] = fmaf(a2, b.w, O[2][3]);
            O[3][0] = fmaf(a3, b.x, O[3][0]);
            O[3][1] = fmaf(a3, b.y, O[3][1]);
            O[3][2] = fmaf(a3, b.z, O[3][2]);
            O[3][3] = fmaf(a3, b.w, O[3][3]);
        }
    }

    #pragma unroll
    for (int i = 0; i < 4; i++) {
        float l = lsum[i];
        l += __shfl_xor_sync(0xffffffffu, l, 1);
        l += __shfl_xor_sync(0xffffffffu, l, 2);
        l += __shfl_xor_sync(0xffffffffu, l, 4);
        l += __shfl_xor_sync(0xffffffffu, l, 8);
        const float inv = 1.0f / l;
        const int m = bb * NN + i0 + r0 + i;
        float4 o = make_float4(O[i][0] * inv, O[i][1] * inv,
                               O[i][2] * inv, O[i][3] * inv);
        *(float4*)(att + (size_t)m * DD + hh * HD + c0) = o;
    }
}

// ---------------------------------------------------------------------------
// Launch
// ---------------------------------------------------------------------------
extern "C" void kernel_launch(void* const* d_in, const int* in_sizes, int n_in,
                              void* d_out, int out_size)
{
    (void)in_sizes; (void)n_in; (void)out_size;
    const float* x  = (const float*)d_in[0];
    const float* wq = (const float*)d_in[1];
    const float* bq = (const float*)d_in[2];
    const float* wk = (const float*)d_in[3];
    const float* bk = (const float*)d_in[4];
    const float* wv = (const float*)d_in[5];
    const float* bv = (const float*)d_in[6];
    const float* wo = (const float*)d_in[7];
    const float* bo = (const float*)d_in[8];
    float* out = (float*)d_out;

    float *qp, *kp, *vp, *q2p, *k2p, *ap;
    cudaGetSymbolAddress((void**)&qp,  g_q);
    cudaGetSymbolAddress((void**)&kp,  g_k);
    cudaGetSymbolAddress((void**)&vp,  g_v);
    cudaGetSymbolAddress((void**)&q2p, g_q2);
    cudaGetSymbolAddress((void**)&k2p, g_k2);
    cudaGetSymbolAddress((void**)&ap,  g_att);

    cudaFuncSetAttribute(wg_gemm<0>,
                         cudaFuncAttributeMaxDynamicSharedMemorySize, GEMM_SMEM);
    cudaFuncSetAttribute(wg_gemm<1>,
                         cudaFuncAttributeMaxDynamicSharedMemorySize, GEMM_SMEM);
    cudaFuncSetAttribute(attn_kernel,
                         cudaFuncAttributeMaxDynamicSharedMemorySize, ATT_SMEM_BYTES);

    const dim3 gb(DD / 64, MM / 128);   // (16, 32)
    wg_gemm<1><<<gb, 256, GEMM_SMEM>>>(x, wq, bq, qp);
    wg_gemm<1><<<gb, 256, GEMM_SMEM>>>(x, wk, bk, kp);
    wg_gemm<1><<<gb, 256, GEMM_SMEM>>>(x, wv, bv, vp);

    rownorm_kernel<<<ROWS / 256, 256>>>(qp, q2p);
    rownorm_kernel<<<ROWS / 256, 256>>>(kp, k2p);

    attn_kernel<<<dim3(NN / 64, BB * HH), 256, ATT_SMEM_BYTES>>>(
        qp, kp, vp, q2p, k2p, ap);

    wg_gemm<0><<<gb, 256, GEMM_SMEM>>>(ap, wo, bo, out);
}

// round 17
// speedup vs baseline: 3.2352x; 2.1220x over previous
#include <cuda_runtime.h>
#include <cuda_fp16.h>
#include <math.h>
#include <stdint.h>

// Problem constants (B=2, N=2048, D=1024, H=16, hd=64)
#define BB   2
#define NN   2048
#define DD   1024
#define HH   16
#define HD   64
#define MM   (BB * NN)        // 4096 tokens
#define ROWS (BB * HH * NN)   // 65536

// Scratch device globals (no allocations allowed)
__device__ float  g_q[ROWS * HD];          // fp32 head layout (B,H,N,hd)
__device__ float  g_k[ROWS * HD];
__device__ float  g_v[ROWS * HD];
__device__ __half g_qh[ROWS * HD];         // fp16 head layout
__device__ __half g_kh[ROWS * HD];
__device__ __half g_vt[ROWS * HD];         // fp16 TRANSPOSED: [bh][d][n]
__device__ float  g_q2[ROWS];
__device__ float  g_k2[ROWS];
__device__ float  g_att[MM * DD];

// ===========================================================================
// Helpers (baseline PTX only — sm_80-era mma.sync / ldmatrix)
// ===========================================================================
__device__ __forceinline__ uint32_t smem_u32(const void* p) {
    uint32_t a;
    asm("{ .reg .u64 t; cvta.to.shared.u64 t, %1; cvt.u32.u64 %0, t; }"
        : "=r"(a) : "l"(p));
    return a;
}

__device__ __forceinline__ void ldx4(uint32_t* r, uint32_t addr) {
    asm volatile("ldmatrix.sync.aligned.m8n8.x4.shared.b16 {%0,%1,%2,%3}, [%4];"
                 : "=r"(r[0]), "=r"(r[1]), "=r"(r[2]), "=r"(r[3]) : "r"(addr));
}

__device__ __forceinline__ void mma_bf(float* c, const uint32_t* a,
                                       uint32_t b0, uint32_t b1) {
    asm volatile(
        "mma.sync.aligned.m16n8k16.row.col.f32.bf16.bf16.f32 "
        "{%0,%1,%2,%3}, {%4,%5,%6,%7}, {%8,%9}, {%0,%1,%2,%3};"
        : "+f"(c[0]), "+f"(c[1]), "+f"(c[2]), "+f"(c[3])
        : "r"(a[0]), "r"(a[1]), "r"(a[2]), "r"(a[3]), "r"(b0), "r"(b1));
}

__device__ __forceinline__ void mma_fp16(float* c, const uint32_t* a,
                                         uint32_t b0, uint32_t b1) {
    asm volatile(
        "mma.sync.aligned.m16n8k16.row.col.f32.f16.f16.f32 "
        "{%0,%1,%2,%3}, {%4,%5,%6,%7}, {%8,%9}, {%0,%1,%2,%3};"
        : "+f"(c[0]), "+f"(c[1]), "+f"(c[2]), "+f"(c[3])
        : "r"(a[0]), "r"(a[1]), "r"(a[2]), "r"(a[3]), "r"(b0), "r"(b1));
}

// fp32 -> (hi bf16 = truncation, lo bf16 = rn(x - hi)), packed pairs
__device__ __forceinline__ void split4(float4 f, uint32_t& h01, uint32_t& h23,
                                       uint32_t& l01, uint32_t& l23) {
    uint32_t bx = __float_as_uint(f.x), by = __float_as_uint(f.y);
    uint32_t bz = __float_as_uint(f.z), bw = __float_as_uint(f.w);
    h01 = __byte_perm(bx, by, 0x7632);
    h23 = __byte_perm(bz, bw, 0x7632);
    float lx = f.x - __uint_as_float(bx & 0xFFFF0000u);
    float ly = f.y - __uint_as_float(by & 0xFFFF0000u);
    float lz = f.z - __uint_as_float(bz & 0xFFFF0000u);
    float lw = f.w - __uint_as_float(bw & 0xFFFF0000u);
    asm("cvt.rn.bf16x2.f32 %0, %1, %2;" : "=r"(l01) : "f"(ly), "f"(lx));
    asm("cvt.rn.bf16x2.f32 %0, %1, %2;" : "=r"(l23) : "f"(lw), "f"(lz));
}

// ===========================================================================
// Split-bf16 tensor-core GEMM (unchanged from R14 pass)
// ===========================================================================
#define LDP   80
#define P_AH  0
#define P_AL  10240
#define P_BH  20480
#define P_BL  25600
#define BUF_BYTES 30720
#define GEMM_SMEM (2 * BUF_BYTES)

template <int MODE>
__global__ __launch_bounds__(256, 2)
void wg_gemm(const float* __restrict__ A, const float* __restrict__ W,
             const float* __restrict__ bias, float* __restrict__ C)
{
    extern __shared__ char smc[];
    const uint32_t sb = smem_u32(smc);
    const int tid = threadIdx.x;
    const int wid = tid >> 5;
    const int lid = tid & 31;
    const int wm  = wid & 3;
    const int wn  = wid >> 2;
    const int m0  = blockIdx.y * 128;
    const int n0  = blockIdx.x * 64;

    const int arow = tid >> 3;
    const int aq   = tid & 7;
    const float* Abase = A + (size_t)(m0 + arow) * DD + aq * 4;
    const float* Wbase = W + (size_t)(n0 + arow) * DD + aq * 4;
    const uint32_t soff = (uint32_t)(arow * LDP + aq * 8);

    float acc[2][4][4];
    #pragma unroll
    for (int mb = 0; mb < 2; mb++)
        #pragma unroll
        for (int nt = 0; nt < 4; nt++)
            #pragma unroll
            for (int e = 0; e < 4; e++) acc[mb][nt][e] = 0.0f;

    float4 pa[4], pb[2];
    #pragma unroll
    for (int i = 0; i < 4; i++) pa[i] = *(const float4*)(Abase + (size_t)i * 32 * DD);
    #pragma unroll
    for (int i = 0; i < 2; i++) pb[i] = *(const float4*)(Wbase + (size_t)i * 32 * DD);
    {
        const uint32_t bufb = sb;
        #pragma unroll
        for (int i = 0; i < 4; i++) {
            uint32_t h01, h23, l01, l23;
            split4(pa[i], h01, h23, l01, l23);
            asm volatile("st.shared.v2.b32 [%0], {%1, %2};"
                         :: "r"(bufb + P_AH + soff + i * 32 * LDP), "r"(h01), "r"(h23) : "memory");
            asm volatile("st.shared.v2.b32 [%0], {%1, %2};"
                         :: "r"(bufb + P_AL + soff + i * 32 * LDP), "r"(l01), "r"(l23) : "memory");
        }
        #pragma unroll
        for (int i = 0; i < 2; i++) {
            uint32_t h01, h23, l01, l23;
            split4(pb[i], h01, h23, l01, l23);
            asm volatile("st.shared.v2.b32 [%0], {%1, %2};"
                         :: "r"(bufb + P_BH + soff + i * 32 * LDP), "r"(h01), "r"(h23) : "memory");
            asm volatile("st.shared.v2.b32 [%0], {%1, %2};"
                         :: "r"(bufb + P_BL + soff + i * 32 * LDP), "r"(l01), "r"(l23) : "memory");
        }
    }
    __syncthreads();

    #pragma unroll 1
    for (int c = 0; c < 32; c++) {
        const uint32_t bufb = sb + (uint32_t)(c & 1) * BUF_BYTES;
        const bool hasnext = (c + 1 < 32);
        if (hasnext) {
            const int k0 = (c + 1) * 32;
            #pragma unroll
            for (int i = 0; i < 4; i++)
                pa[i] = *(const float4*)(Abase + (size_t)i * 32 * DD + k0);
            #pragma unroll
            for (int i = 0; i < 2; i++)
                pb[i] = *(const float4*)(Wbase + (size_t)i * 32 * DD + k0);
        }

        #pragma unroll
        for (int kb = 0; kb < 2; kb++) {
            const uint32_t lmrow = (uint32_t)(lid & 15) * LDP;
            const uint32_t lmcol = (uint32_t)(kb * 32 + (lid >> 4) * 16);
            const uint32_t aA = bufb + P_AH + (uint32_t)(wm * 32) * LDP + lmrow + lmcol;
            const uint32_t aB = bufb + P_BH + (uint32_t)(wn * 32) * LDP + lmrow + lmcol;
            uint32_t ah[2][4], al[2][4], bh[2][4], bl[2][4];
            ldx4(ah[0], aA);
            ldx4(ah[1], aA + 16 * LDP);
            ldx4(al[0], aA + (P_AL - P_AH));
            ldx4(al[1], aA + (P_AL - P_AH) + 16 * LDP);
            ldx4(bh[0], aB);
            ldx4(bh[1], aB + 16 * LDP);
            ldx4(bl[0], aB + (P_BL - P_BH));
            ldx4(bl[1], aB + (P_BL - P_BH) + 16 * LDP);
            #pragma unroll
            for (int mb = 0; mb < 2; mb++)
                #pragma unroll
                for (int nt = 0; nt < 4; nt++) {
                    const int nb = nt >> 1, s = nt & 1;
                    mma_bf(acc[mb][nt], ah[mb], bh[nb][s], bh[nb][2 + s]);
                    mma_bf(acc[mb][nt], ah[mb], bl[nb][s], bl[nb][2 + s]);
                    mma_bf(acc[mb][nt], al[mb], bh[nb][s], bh[nb][2 + s]);
                }
        }

        if (hasnext) {
            const uint32_t nb2 = sb + (uint32_t)((c + 1) & 1) * BUF_BYTES;
            #pragma unroll
            for (int i = 0; i < 4; i++) {
                uint32_t h01, h23, l01, l23;
                split4(pa[i], h01, h23, l01, l23);
                asm volatile("st.shared.v2.b32 [%0], {%1, %2};"
                             :: "r"(nb2 + P_AH + soff + i * 32 * LDP), "r"(h01), "r"(h23) : "memory");
                asm volatile("st.shared.v2.b32 [%0], {%1, %2};"
                             :: "r"(nb2 + P_AL + soff + i * 32 * LDP), "r"(l01), "r"(l23) : "memory");
            }
            #pragma unroll
            for (int i = 0; i < 2; i++) {
                uint32_t h01, h23, l01, l23;
                split4(pb[i], h01, h23, l01, l23);
                asm volatile("st.shared.v2.b32 [%0], {%1, %2};"
                             :: "r"(nb2 + P_BH + soff + i * 32 * LDP), "r"(h01), "r"(h23) : "memory");
                asm volatile("st.shared.v2.b32 [%0], {%1, %2};"
                             :: "r"(nb2 + P_BL + soff + i * 32 * LDP), "r"(l01), "r"(l23) : "memory");
            }
        }
        __syncthreads();
    }

    const int gid = lid >> 2;
    const int tig = lid & 3;
    #pragma unroll
    for (int mb = 0; mb < 2; mb++) {
        #pragma unroll
        for (int nt = 0; nt < 4; nt++) {
            const int col  = wn * 32 + nt * 8 + tig * 2;
            const int gcol = n0 + col;
            const float bx = bias[gcol];
            const float by = bias[gcol + 1];
            const int row0 = m0 + wm * 32 + mb * 16 + gid;
            const int row1 = row0 + 8;
            float2 o0 = make_float2(acc[mb][nt][0] + bx, acc[mb][nt][1] + by);
            float2 o1 = make_float2(acc[mb][nt][2] + bx, acc[mb][nt][3] + by);
            if (MODE == 0) {
                *(float2*)(C + (size_t)row0 * DD + gcol) = o0;
                *(float2*)(C + (size_t)row1 * DD + gcol) = o1;
            } else {
                const int h = n0 >> 6;
                const int b0i = row0 >> 11, n0i = row0 & 2047;
                const int b1i = row1 >> 11, n1i = row1 & 2047;
                *(float2*)(C + (((size_t)(b0i * HH + h)) * NN + n0i) * HD + col) = o0;
                *(float2*)(C + (((size_t)(b1i * HH + h)) * NN + n1i) * HD + col) = o1;
            }
        }
    }
}

// ---------------------------------------------------------------------------
// fp32 -> fp16 convert + row squared-norm (norm computed from ROUNDED halves
// so d2 = q2 + k2 - 2 qh.kh is self-consistent).
// ---------------------------------------------------------------------------
__global__ __launch_bounds__(256)
void cvt_qk(const float* __restrict__ in, __half* __restrict__ oh,
            float* __restrict__ norm)
{
    const int r = blockIdx.x * blockDim.x + threadIdx.x;
    if (r >= ROWS) return;
    const float4* p = (const float4*)(in + (size_t)r * HD);
    uint2* o = (uint2*)(oh + (size_t)r * HD);
    float s = 0.0f;
    #pragma unroll
    for (int i = 0; i < 16; i++) {
        float4 t = p[i];
        __half2 h0 = __floats2half2_rn(t.x, t.y);
        __half2 h1 = __floats2half2_rn(t.z, t.w);
        float2 f0 = __half22float2(h0);
        float2 f1 = __half22float2(h1);
        s = fmaf(f0.x, f0.x, s);
        s = fmaf(f0.y, f0.y, s);
        s = fmaf(f1.x, f1.x, s);
        s = fmaf(f1.y, f1.y, s);
        uint2 u;
        u.x = *reinterpret_cast<uint32_t*>(&h0);
        u.y = *reinterpret_cast<uint32_t*>(&h1);
        o[i] = u;
    }
    norm[r] = s;
}

// ---------------------------------------------------------------------------
// V: fp32 (bh, n, d) -> fp16 TRANSPOSED (bh, d, n) via SMEM tile
// ---------------------------------------------------------------------------
#define LDH 72   // halves per SMEM row (144 B = 9 x 16 B: conflict-free ldmatrix)

__global__ __launch_bounds__(256)
void cvt_v(const float* __restrict__ v, __half* __restrict__ vt)
{
    __shared__ __half sj[64 * LDH];   // [j][d]
    const int bh = blockIdx.y;
    const int j0 = blockIdx.x * 64;
    const int t  = threadIdx.x;
    {
        const int j = t >> 2, dseg = (t & 3) * 16;
        const float4* src = (const float4*)(v + ((size_t)bh * NN + j0 + j) * HD + dseg);
        #pragma unroll
        for (int i = 0; i < 4; i++) {
            float4 x = src[i];
            __half2 h0 = __floats2half2_rn(x.x, x.y);
            __half2 h1 = __floats2half2_rn(x.z, x.w);
            uint2 u;
            u.x = *reinterpret_cast<uint32_t*>(&h0);
            u.y = *reinterpret_cast<uint32_t*>(&h1);
            *(uint2*)&sj[j * LDH + dseg + i * 4] = u;
        }
    }
    __syncthreads();
    {
        const int d = t >> 2, jseg = (t & 3) * 16;
        __half2* dst = (__half2*)(vt + ((size_t)bh * HD + d) * NN + j0 + jseg);
        #pragma unroll
        for (int p = 0; p < 8; p++) {
            __half a = sj[(jseg + 2 * p) * LDH + d];
            __half b = sj[(jseg + 2 * p + 1) * LDH + d];
            dst[p] = __halves2half2(a, b);
        }
    }
}

// ---------------------------------------------------------------------------
// Tensor-core flash attention (fp16 mma.sync), no max subtraction.
// One CTA = (b,h) x 64 query rows; 8 warps = 4m x 2n; warp tile 16x32.
// ---------------------------------------------------------------------------
struct AttSmem {
    __half qh[64 * LDH];
    __half kh[64 * LDH];
    __half vt[64 * LDH];   // [d][j]
    __half ps[64 * LDH];   // [i][j]
    float  k2s[64];
    float  lred[64 * 2];
};

__global__ __launch_bounds__(256, 2)
void attn_tc(const __half* __restrict__ qh, const __half* __restrict__ kh,
             const __half* __restrict__ vt, const float* __restrict__ q2,
             const float* __restrict__ k2, float* __restrict__ att)
{
    __shared__ AttSmem s;
    const int tid = threadIdx.x;
    const int wid = tid >> 5;
    const int lid = tid & 31;
    const int wm  = wid & 3;          // rows 16*wm .. +15
    const int wn  = wid >> 2;         // cols 32*wn .. +31
    const int gid = lid >> 2;
    const int tig = lid & 3;
    const int bh  = blockIdx.y;
    const int i0  = blockIdx.x * 64;
    const int bb  = bh >> 4;
    const int hh  = bh & 15;

    const uint32_t sq = smem_u32(s.qh);
    const uint32_t sk = smem_u32(s.kh);
    const uint32_t sv = smem_u32(s.vt);
    const uint32_t sp = smem_u32(s.ps);
    const uint32_t LDHB = LDH * 2;    // 144 bytes/row

    // ldmatrix lane addressing (shared across all fragment loads)
    const uint32_t lrow = (uint32_t)(lid & 15) * LDHB;
    const uint32_t lcol = (uint32_t)(lid >> 4) * 16;

    // Load Q tile (64x64 fp16) once
    {
        const int r = tid >> 2, seg = (tid & 3) * 16;
        const uint4* src = (const uint4*)(qh + ((size_t)bh * NN + i0 + r) * HD + seg);
        *(uint4*)&s.qh[r * LDH + seg]     = src[0];
        *(uint4*)&s.qh[r * LDH + seg + 8] = src[1];
    }

    const int ra = 16 * wm + gid;     // accumulator row a (within tile)
    const float q2a = q2[(size_t)bh * NN + i0 + ra];
    const float q2b = q2[(size_t)bh * NN + i0 + ra + 8];

    float O[4][4];
    #pragma unroll
    for (int nt = 0; nt < 4; nt++)
        #pragma unroll
        for (int e = 0; e < 4; e++) O[nt][e] = 0.0f;
    float psa = 0.0f, psb = 0.0f;

    #pragma unroll 1
    for (int j0 = 0; j0 < NN; j0 += 64) {
        __syncthreads();   // protect kh/vt/ps from prior readers
        {
            const int r = tid >> 2, seg = (tid & 3) * 16;
            const uint4* srck = (const uint4*)(kh + ((size_t)bh * NN + j0 + r) * HD + seg);
            *(uint4*)&s.kh[r * LDH + seg]     = srck[0];
            *(uint4*)&s.kh[r * LDH + seg + 8] = srck[1];
            const uint4* srcv = (const uint4*)(vt + ((size_t)bh * HD + r) * NN + j0 + seg);
            *(uint4*)&s.vt[r * LDH + seg]     = srcv[0];
            *(uint4*)&s.vt[r * LDH + seg + 8] = srcv[1];
        }
        if (tid < 64) s.k2s[tid] = k2[(size_t)bh * NN + j0 + tid];
        __syncthreads();

        // ---- S = Q K^T ----
        float acc[4][4];
        #pragma unroll
        for (int nt = 0; nt < 4; nt++)
            #pragma unroll
            for (int e = 0; e < 4; e++) acc[nt][e] = 0.0f;

        #pragma unroll
        for (int ks = 0; ks < 4; ks++) {
            const uint32_t co = (uint32_t)ks * 32 + lcol;
            uint32_t af[4], b0[4], b1[4];
            ldx4(af, sq + (uint32_t)(16 * wm) * LDHB + lrow + co);
            ldx4(b0, sk + (uint32_t)(32 * wn) * LDHB + lrow + co);
            ldx4(b1, sk + (uint32_t)(32 * wn + 16) * LDHB + lrow + co);
            #pragma unroll
            for (int nt = 0; nt < 4; nt++) {
                const uint32_t* bf = (nt < 2) ? b0 : b1;
                const int sx = nt & 1;
                mma_fp16(acc[nt], af, bf[sx], bf[2 + sx]);
            }
        }

        // ---- P = exp(-sqrt(d2)), store fp16 to SMEM ----
        #pragma unroll
        for (int nt = 0; nt < 4; nt++) {
            const int cb = 32 * wn + nt * 8 + 2 * tig;
            const float2 kk = *(const float2*)&s.k2s[cb];
            float d0 = fmaxf(fmaf(acc[nt][0], -2.0f, q2a + kk.x), 1e-12f);
            float d1 = fmaxf(fmaf(acc[nt][1], -2.0f, q2a + kk.y), 1e-12f);
            float d2_ = fmaxf(fmaf(acc[nt][2], -2.0f, q2b + kk.x), 1e-12f);
            float d3 = fmaxf(fmaf(acc[nt][3], -2.0f, q2b + kk.y), 1e-12f);
            float p0 = __expf(-d0 * rsqrtf(d0));
            float p1 = __expf(-d1 * rsqrtf(d1));
            float p2 = __expf(-d2_ * rsqrtf(d2_));
            float p3 = __expf(-d3 * rsqrtf(d3));
            psa += p0 + p1;
            psb += p2 + p3;
            *(__half2*)&s.ps[ra * LDH + cb]       = __floats2half2_rn(p0, p1);
            *(__half2*)&s.ps[(ra + 8) * LDH + cb] = __floats2half2_rn(p2, p3);
        }
        __syncthreads();

        // ---- O += P V  (A = Ps rows, B = Vt rows d, cols j) ----
        #pragma unroll
        for (int ks = 0; ks < 4; ks++) {
            const uint32_t co = (uint32_t)ks * 32 + lcol;
            uint32_t af[4], b0[4], b1[4];
            ldx4(af, sp + (uint32_t)(16 * wm) * LDHB + lrow + co);
            ldx4(b0, sv + (uint32_t)(32 * wn) * LDHB + lrow + co);
            ldx4(b1, sv + (uint32_t)(32 * wn + 16) * LDHB + lrow + co);
            #pragma unroll
            for (int nt = 0; nt < 4; nt++) {
                const uint32_t* bf = (nt < 2) ? b0 : b1;
                const int sx = nt & 1;
                mma_fp16(O[nt], af, bf[sx], bf[2 + sx]);
            }
        }
    }

    // ---- final row-sum reduction + normalize + write ----
    psa += __shfl_xor_sync(0xffffffffu, psa, 1);
    psa += __shfl_xor_sync(0xffffffffu, psa, 2);
    psb += __shfl_xor_sync(0xffffffffu, psb, 1);
    psb += __shfl_xor_sync(0xffffffffu, psb, 2);
    __syncthreads();
    if (tig == 0) {
        s.lred[ra * 2 + wn]       = psa;
        s.lred[(ra + 8) * 2 + wn] = psb;
    }
    __syncthreads();
    const float inva = 1.0f / (s.lred[ra * 2] + s.lred[ra * 2 + 1]);
    const float invb = 1.0f / (s.lred[(ra + 8) * 2] + s.lred[(ra + 8) * 2 + 1]);

    const int ma = bb * NN + i0 + ra;
    #pragma unroll
    for (int nt = 0; nt < 4; nt++) {
        const int col = hh * 64 + 32 * wn + nt * 8 + 2 * tig;
        *(float2*)(att + (size_t)ma * DD + col) =
            make_float2(O[nt][0] * inva, O[nt][1] * inva);
        *(float2*)(att + (size_t)(ma + 8) * DD + col) =
            make_float2(O[nt][2] * invb, O[nt][3] * invb);
    }
}

// ---------------------------------------------------------------------------
// Launch
// ---------------------------------------------------------------------------
extern "C" void kernel_launch(void* const* d_in, const int* in_sizes, int n_in,
                              void* d_out, int out_size)
{
    (void)in_sizes; (void)n_in; (void)out_size;
    const float* x  = (const float*)d_in[0];
    const float* wq = (const float*)d_in[1];
    const float* bq = (const float*)d_in[2];
    const float* wk = (const float*)d_in[3];
    const float* bk = (const float*)d_in[4];
    const float* wv = (const float*)d_in[5];
    const float* bv = (const float*)d_in[6];
    const float* wo = (const float*)d_in[7];
    const float* bo = (const float*)d_in[8];
    float* out = (float*)d_out;

    float *qp, *kp, *vp, *q2p, *k2p, *ap;
    __half *qhp, *khp, *vtp;
    cudaGetSymbolAddress((void**)&qp,  g_q);
    cudaGetSymbolAddress((void**)&kp,  g_k);
    cudaGetSymbolAddress((void**)&vp,  g_v);
    cudaGetSymbolAddress((void**)&qhp, g_qh);
    cudaGetSymbolAddress((void**)&khp, g_kh);
    cudaGetSymbolAddress((void**)&vtp, g_vt);
    cudaGetSymbolAddress((void**)&q2p, g_q2);
    cudaGetSymbolAddress((void**)&k2p, g_k2);
    cudaGetSymbolAddress((void**)&ap,  g_att);

    cudaFuncSetAttribute(wg_gemm<0>,
                         cudaFuncAttributeMaxDynamicSharedMemorySize, GEMM_SMEM);
    cudaFuncSetAttribute(wg_gemm<1>,
                         cudaFuncAttributeMaxDynamicSharedMemorySize, GEMM_SMEM);

    const dim3 gb(DD / 64, MM / 128);   // (16, 32)
    wg_gemm<1><<<gb, 256, GEMM_SMEM>>>(x, wq, bq, qp);
    wg_gemm<1><<<gb, 256, GEMM_SMEM>>>(x, wk, bk, kp);
    wg_gemm<1><<<gb, 256, GEMM_SMEM>>>(x, wv, bv, vp);

    cvt_qk<<<ROWS / 256, 256>>>(qp, qhp, q2p);
    cvt_qk<<<ROWS / 256, 256>>>(kp, khp, k2p);
    cvt_v<<<dim3(NN / 64, BB * HH), 256>>>(vp, vtp);

    attn_tc<<<dim3(NN / 64, BB * HH), 256>>>(qhp, khp, vtp, q2p, k2p, ap);

    wg_gemm<0><<<gb, 256, GEMM_SMEM>>>(ap, wo, bo, out);
}